// round 16
// baseline (speedup 1.0000x reference)
#include <cuda_runtime.h>
#include <cuda_fp16.h>
#include <cstring>

#define BB 2
#define NN 4096
#define DD 512
#define HH 8
#define DH 64
#define MM 1024
#define NK 5120          // NN + MM
#define LSEQ 5119        // NK - 1

// ---------------- fp16 helpers -----------------------------------------------
__device__ __forceinline__ unsigned rnd2(float x, float y) {
    __half2 h = __floats2half2_rn(x, y);
    unsigned u; memcpy(&u, &h, 4); return u;
}
__device__ __forceinline__ void mma16816(float c[4], const unsigned a[4],
                                         unsigned b0, unsigned b1) {
    asm("mma.sync.aligned.m16n8k16.row.col.f32.f16.f16.f32 "
        "{%0,%1,%2,%3},{%4,%5,%6,%7},{%8,%9},{%0,%1,%2,%3};"
        : "+f"(c[0]), "+f"(c[1]), "+f"(c[2]), "+f"(c[3])
        : "r"(a[0]), "r"(a[1]), "r"(a[2]), "r"(a[3]), "r"(b0), "r"(b1));
}
__device__ __forceinline__ unsigned su(const void* p) {
    return (unsigned)__cvta_generic_to_shared(p);
}
__device__ __forceinline__ void ldsm4(unsigned* r, unsigned addr) {
    asm volatile("ldmatrix.sync.aligned.m8n8.x4.shared.b16 {%0,%1,%2,%3}, [%4];"
                 : "=r"(r[0]), "=r"(r[1]), "=r"(r[2]), "=r"(r[3]) : "r"(addr));
}
__device__ __forceinline__ void ldsm4t(unsigned* r, unsigned addr) {
    asm volatile("ldmatrix.sync.aligned.m8n8.x4.trans.shared.b16 {%0,%1,%2,%3}, [%4];"
                 : "=r"(r[0]), "=r"(r[1]), "=r"(r[2]), "=r"(r[3]) : "r"(addr));
}
__device__ __forceinline__ void cpa16(void* s, const void* g) {
    asm volatile("cp.async.cg.shared.global [%0], [%1], 16;" :: "r"(su(s)), "l"(g));
}
__device__ __forceinline__ void cp_commit() { asm volatile("cp.async.commit_group;"); }
__device__ __forceinline__ void cp_wait1()  { asm volatile("cp.async.wait_group 1;"); }
__device__ __forceinline__ void cp_wait0()  { asm volatile("cp.async.wait_group 0;"); }

// ---------------- scratch ----------------------------------------------------
__device__ __half    g_xf[BB * NN * DD];   // LN out fp16
__device__ __half    g_qf[BB * NN * DD];   // q, pre-scaled fp16
__device__ __half    g_kp[BB * NK * DD];   // pre-PEG k fp16 (tail = mem)
__device__ __half    g_vp[BB * NK * DD];   // pre-PEG v fp16 (tail = mem)
__device__ __half    g_kf[BB * NK * DD];   // post-PEG K fp16
__device__ __half    g_vf[BB * NK * DD];   // post-PEG V fp16
__device__ __half    g_af[BB * NN * DD];   // attention out fp16
__device__ __half    g_wq[DD * 3 * DD];    // w_qkv fp16
__device__ __half    g_wo[DD * DD];        // w_out fp16
__device__ float     g_mq[BB * NN * HH];   // ||q_row|| per head (q pre-scaled)
__device__ unsigned  g_mku[BB * HH];       // max_k ||k_k|| per (b,h), float-as-uint

// ---------------- fp32 -> fp16 rounder (weights) -----------------------------
__global__ void round_kernel(const float* __restrict__ src,
                             __half* __restrict__ dst, int n4) {
    int i = blockIdx.x * 256 + threadIdx.x;
    if (i >= n4) return;
    float4 v = ((const float4*)src)[i];
    ((uint2*)dst)[i] = make_uint2(rnd2(v.x, v.y), rnd2(v.z, v.w));
}

// ---------------- mem tail rounder + g_mku init ------------------------------
__global__ void mem_round_kernel(const float* __restrict__ mem) {
    int i = blockIdx.x * 256 + threadIdx.x;
    if (i < BB * HH) g_mku[i] = 0u;
    if (i >= BB * MM * 512 / 4) return;
    float4 v = ((const float4*)mem)[i];
    uint2 pk = make_uint2(rnd2(v.x, v.y), rnd2(v.z, v.w));
    int gi = i << 2;
    int b = gi / (MM * 512);
    int rem = gi - b * (MM * 512);
    size_t off = (((size_t)b * NK + NN) * 512 + rem) >> 2;
    ((uint2*)g_kp)[off] = pk;
    ((uint2*)g_vp)[off] = pk;
}

// ---------------- LayerNorm (writes fp16) ------------------------------------
__global__ void ln_kernel(const float* __restrict__ x,
                          const float* __restrict__ g,
                          const float* __restrict__ bt) {
    int row = blockIdx.x;
    int t = threadIdx.x;
    const float4* xr = (const float4*)(x + (size_t)row * DD);
    float4 v = xr[t];
    float s  = v.x + v.y + v.z + v.w;
    float s2 = v.x*v.x + v.y*v.y + v.z*v.z + v.w*v.w;
    #pragma unroll
    for (int o = 16; o > 0; o >>= 1) {
        s  += __shfl_xor_sync(0xffffffffu, s,  o);
        s2 += __shfl_xor_sync(0xffffffffu, s2, o);
    }
    __shared__ float a1[4], a2[4];
    int w = t >> 5;
    if ((t & 31) == 0) { a1[w] = s; a2[w] = s2; }
    __syncthreads();
    s  = a1[0] + a1[1] + a1[2] + a1[3];
    s2 = a2[0] + a2[1] + a2[2] + a2[3];
    float mu  = s * (1.0f / 512.0f);
    float var = s2 * (1.0f / 512.0f) - mu * mu;
    float rs  = rsqrtf(var + 1e-5f);
    float4 gg = ((const float4*)g)[t];
    float4 bb = ((const float4*)bt)[t];
    float4 o4;
    o4.x = (v.x - mu) * rs * gg.x + bb.x;
    o4.y = (v.y - mu) * rs * gg.y + bb.y;
    o4.z = (v.z - mu) * rs * gg.z + bb.z;
    o4.w = (v.w - mu) * rs * gg.w + bb.w;
    ((uint2*)(g_xf + (size_t)row * DD))[t] =
        make_uint2(rnd2(o4.x, o4.y), rnd2(o4.z, o4.w));
}

// ---------------- q norms: one warp per (b*NN+n, h) --------------------------
__global__ void qnorm_kernel() {
    int idx = blockIdx.x * 8 + (threadIdx.x >> 5);
    int lane = threadIdx.x & 31;
    int bn = idx >> 3, h = idx & 7;
    unsigned u = *(const unsigned*)(g_qf + (size_t)bn * 512 + h * 64 + lane * 2);
    __half2 hv; memcpy(&hv, &u, 4);
    float2 f = __half22float2(hv);
    float s = f.x * f.x + f.y * f.y;
    #pragma unroll
    for (int o = 16; o > 0; o >>= 1) s += __shfl_xor_sync(0xffffffffu, s, o);
    if (lane == 0) g_mq[idx] = sqrtf(s);
}

// ---------------- fp16 1-term mma GEMM, 128x128 tile, 3-stage cp.async ------
#define ASTR 24
#define WSTR 136
__global__ __launch_bounds__(256)
void mma_gemm_kernel(const __half* __restrict__ Wh,
                     const float* __restrict__ bias,
                     float* __restrict__ dout, int cn, int mode) {
    const __half* Ah = mode ? g_af : g_xf;
    __shared__ __align__(16) __half sA[3][128 * ASTR];
    __shared__ __align__(16) __half sW[3][16 * WSTR];
    int tid = threadIdx.x, w = tid >> 5, lane = tid & 31;
    int gq = lane >> 2, qq = lane & 3;
    int lt = lane >> 3, lr = lane & 7;
    int row0 = blockIdx.y * 128, col0 = blockIdx.x * 128;
    int wm = w >> 1, wn = w & 1;
    float acc[2][8][4];
    #pragma unroll
    for (int mf = 0; mf < 2; mf++)
        #pragma unroll
        for (int nf = 0; nf < 8; nf++)
            #pragma unroll
            for (int c = 0; c < 4; c++) acc[mf][nf][c] = 0.f;

    auto load_tile = [&](int t, int s) {
        int kt = t * 16;
        {
            int r = tid >> 1, e = tid & 1;
            cpa16(&sA[s][r * ASTR + 8 * e], Ah + (size_t)(row0 + r) * 512 + kt + 8 * e);
        }
        {
            int r = tid >> 4, e = tid & 15;
            cpa16(&sW[s][r * WSTR + 8 * e], Wh + (size_t)(kt + r) * cn + col0 + 8 * e);
        }
        cp_commit();
    };

    load_tile(0, 0);
    load_tile(1, 1);
    for (int t = 0; t < 32; t++) {
        int s = t % 3;
        if (t + 2 < 32) cp_wait1(); else cp_wait0();
        __syncthreads();
        if (t + 2 < 32) load_tile(t + 2, (t + 2) % 3);
        unsigned ah[2][4];
        #pragma unroll
        for (int mf = 0; mf < 2; mf++) {
            int ar = wm * 32 + mf * 16 + (lt & 1) * 8 + lr;
            int ak = (lt >> 1) * 8;
            ldsm4(ah[mf], su(&sA[s][ar * ASTR + ak]));
        }
        unsigned bh[4][4];
        #pragma unroll
        for (int nh = 0; nh < 4; nh++) {
            int br = (lt & 1) * 8 + lr;
            int bc = wn * 64 + nh * 16 + (lt >> 1) * 8;
            ldsm4t(bh[nh], su(&sW[s][br * WSTR + bc]));
        }
        #pragma unroll
        for (int nf = 0; nf < 8; nf++) {
            unsigned b0 = bh[nf >> 1][(nf & 1) * 2];
            unsigned b1 = bh[nf >> 1][(nf & 1) * 2 + 1];
            #pragma unroll
            for (int mf = 0; mf < 2; mf++)
                mma16816(acc[mf][nf], ah[mf], b0, b1);
        }
    }
    #pragma unroll
    for (int mf = 0; mf < 2; mf++) {
        int rlo = row0 + wm * 32 + mf * 16 + gq;
        #pragma unroll
        for (int nf = 0; nf < 8; nf++) {
            int cl = col0 + wn * 64 + nf * 8 + 2 * qq;
            float* c = acc[mf][nf];
            if (mode == 0) {
                int sel = cl >> 9, c5 = cl & 511;
                #pragma unroll
                for (int half_ = 0; half_ < 2; half_++) {
                    int rr = rlo + half_ * 8;
                    int b = rr >> 12, n = rr & 4095;
                    float v0 = c[2 * half_], v1 = c[2 * half_ + 1];
                    if (sel == 0)
                        *(unsigned*)&g_qf[((size_t)b * NN + n) * 512 + c5] =
                            rnd2(v0 * 0.125f, v1 * 0.125f);
                    else if (sel == 1)
                        *(unsigned*)&g_kp[((size_t)b * NK + n) * 512 + c5] = rnd2(v0, v1);
                    else
                        *(unsigned*)&g_vp[((size_t)b * NK + n) * 512 + c5] = rnd2(v0, v1);
                }
            } else {
                float2 bq = *(const float2*)(bias + cl);
                float2 o0; o0.x = c[0] + bq.x; o0.y = c[1] + bq.y;
                float2 o1; o1.x = c[2] + bq.x; o1.y = c[3] + bq.y;
                *(float2*)(dout + (size_t)rlo * 512 + cl)       = o0;
                *(float2*)(dout + (size_t)(rlo + 8) * 512 + cl) = o1;
            }
        }
    }
}

// ---------------- PEG1D depthwise conv (fp16 in/out) + K norm atomicMax -----
__global__ void peg_kernel(const float* __restrict__ wk, const float* __restrict__ bk,
                           const float* __restrict__ wv, const float* __restrict__ bv) {
    int which = blockIdx.y;
    const float* w    = which ? wv : wk;
    const float* bias = which ? bv : bk;
    const __half* src = which ? g_vp : g_kp;
    __half* df        = which ? g_vf : g_kf;
    int gr = blockIdx.x;
    int b = gr / NK, r = gr - b * NK;
    int tx = threadIdx.x;
    int c = tx << 2;
    const __half* base = src + (size_t)b * NK * 512;
    auto ld4 = [&](int row) -> float4 {
        uint2 u = *(const uint2*)(base + (size_t)row * 512 + c);
        __half2 h0, h1;
        memcpy(&h0, &u.x, 4); memcpy(&h1, &u.y, 4);
        float2 f0 = __half22float2(h0), f1 = __half22float2(h1);
        return make_float4(f0.x, f0.y, f1.x, f1.y);
    };
    float4 xc = ld4(r);
    size_t doff = ((size_t)b * NK + r) * 512 + c;
    float4 o4;
    if (r == 0) {
        o4 = xc;
    } else {
        int t = r - 1;
        float w0[4], w1[4], w2[4];
        #pragma unroll
        for (int j = 0; j < 4; j++) {
            w0[j] = __ldg(w + (c + j) * 3 + 0);
            w1[j] = __ldg(w + (c + j) * 3 + 1);
            w2[j] = __ldg(w + (c + j) * 3 + 2);
        }
        float4 bb = *(const float4*)(bias + c);
        const float4 z4 = make_float4(0.f, 0.f, 0.f, 0.f);
        int p = t & 31;
        float4 L1 = (p > 0)                 ? ld4(r - 1) : z4;
        float4 R1 = (p < 31 && t + 1 < LSEQ)? ld4(r + 1) : z4;
        int u   = (t + 16) % LSEQ;
        int p2p = u % 32;
        int jl  = (u + LSEQ - 17) % LSEQ;
        int jr  = (u + LSEQ - 15) % LSEQ;
        float4 L2 = (p2p > 0)                  ? ld4(1 + jl) : z4;
        float4 R2 = (p2p < 31 && u + 1 < LSEQ) ? ld4(1 + jr) : z4;
        o4.x = xc.x + (w0[0]*L1.x + w1[0]*xc.x + w2[0]*R1.x + bb.x)
                    + (w0[0]*L2.x + w1[0]*xc.x + w2[0]*R2.x + bb.x);
        o4.y = xc.y + (w0[1]*L1.y + w1[1]*xc.y + w2[1]*R1.y + bb.y)
                    + (w0[1]*L2.y + w1[1]*xc.y + w2[1]*R2.y + bb.y);
        o4.z = xc.z + (w0[2]*L1.z + w1[2]*xc.z + w2[2]*R1.z + bb.z)
                    + (w0[2]*L2.z + w1[2]*xc.z + w2[2]*R2.z + bb.z);
        o4.w = xc.w + (w0[3]*L1.w + w1[3]*xc.w + w2[3]*R1.w + bb.w)
                    + (w0[3]*L2.w + w1[3]*xc.w + w2[3]*R2.w + bb.w);
    }
    *(uint2*)(df + doff) = make_uint2(rnd2(o4.x, o4.y), rnd2(o4.z, o4.w));
    if (which == 0) {
        float s = o4.x*o4.x + o4.y*o4.y + o4.z*o4.z + o4.w*o4.w;
        #pragma unroll
        for (int o = 8; o > 0; o >>= 1)
            s += __shfl_xor_sync(0xffffffffu, s, o);
        if ((tx & 15) == 0) {
            int head = tx >> 4;
            atomicMax(&g_mku[b * HH + head], __float_as_uint(sqrtf(s) * 1.001f));
        }
    }
}

// ---------------- flash attention: 4 warps x 32 queries, static-bound sm ----
#define KSTR 72
__global__ __launch_bounds__(128, 3)
void attn_mma_kernel() {
    __shared__ __align__(16) __half Ks[2][64 * KSTR];
    __shared__ __align__(16) __half Vs[2][64 * KSTR];
    int tid = threadIdx.x;
    int w = tid >> 5, lane = tid & 31;
    int gq = lane >> 2, qq = lane & 3;
    int lt = lane >> 3, lr = lane & 7;
    int bh_ = blockIdx.y;
    int b = bh_ >> 3, h = bh_ & 7;
    int q0 = blockIdx.x * 128 + w * 32;       // warp owns 32 query rows

    const __half* kfb = g_kf + ((size_t)b * NK) * 512 + h * 64;
    const __half* vfb = g_vf + ((size_t)b * NK) * 512 + h * 64;

    auto load_tile = [&](int kt, int s) {
        #pragma unroll
        for (int i = 0; i < 4; i++) {
            int idx = tid + 128 * i;
            int row = idx >> 3, e = idx & 7;
            size_t goff = (size_t)(kt + row) * 512 + 8 * e;
            int soff = row * KSTR + 8 * e;
            cpa16(&Ks[s][soff], kfb + goff);
            cpa16(&Vs[s][soff], vfb + goff);
        }
        cp_commit();
    };

    unsigned qh[2][4][4];
    #pragma unroll
    for (int mt = 0; mt < 2; mt++) {
        const __half* qbase = g_qf + ((size_t)b * NN + q0 + mt * 16) * 512 + h * 64;
        #pragma unroll
        for (int kk = 0; kk < 4; kk++)
            #pragma unroll
            for (int cc = 0; cc < 2; cc++)
                #pragma unroll
                for (int rr = 0; rr < 2; rr++) {
                    int row = gq + rr * 8;
                    int dim = kk * 16 + cc * 8 + qq * 2;
                    qh[mt][kk][rr + 2 * cc] =
                        *(const unsigned*)(qbase + (size_t)row * 512 + dim);
                }
    }
    float mk = __uint_as_float(g_mku[b * HH + h]);
    float m0[2], m1[2];
    #pragma unroll
    for (int mt = 0; mt < 2; mt++) {
        m0[mt] = g_mq[((size_t)b * NN + q0 + mt * 16 + gq)     * HH + h] * mk;
        m1[mt] = g_mq[((size_t)b * NN + q0 + mt * 16 + gq + 8) * HH + h] * mk;
    }

    float O[2][8][4];
    #pragma unroll
    for (int mt = 0; mt < 2; mt++)
        #pragma unroll
        for (int j = 0; j < 8; j++)
            #pragma unroll
            for (int c = 0; c < 4; c++) O[mt][j][c] = 0.f;
    float rl0[2] = {0.f, 0.f}, rl1[2] = {0.f, 0.f};

    load_tile(0, 0);
    const int NT = NK / 64;
    for (int t = 0; t < NT; t++) {
        int s = t & 1;
        cp_wait0();
        __syncthreads();
        if (t + 1 < NT) load_tile((t + 1) * 64, s ^ 1);

        unsigned Ph[2][4][4];
        #pragma unroll
        for (int j = 0; j < 8; j++) {
            unsigned bf[8];
            int krow = (8 * j + lr) * KSTR;
            ldsm4(bf,     su(&Ks[s][krow + 8 * lt]));
            ldsm4(bf + 4, su(&Ks[s][krow + 32 + 8 * lt]));
            int kk2 = j >> 1, half_ = j & 1;
            #pragma unroll
            for (int mt = 0; mt < 2; mt++) {
                float c[4] = {0.f, 0.f, 0.f, 0.f};
                #pragma unroll
                for (int kk = 0; kk < 4; kk++)
                    mma16816(c, qh[mt][kk], bf[2 * kk], bf[2 * kk + 1]);
                float p0 = __expf(c[0] - m0[mt]);
                float p1 = __expf(c[1] - m0[mt]);
                float p2 = __expf(c[2] - m1[mt]);
                float p3 = __expf(c[3] - m1[mt]);
                rl0[mt] += p0 + p1; rl1[mt] += p2 + p3;
                Ph[mt][kk2][2 * half_]     = rnd2(p0, p1);
                Ph[mt][kk2][2 * half_ + 1] = rnd2(p2, p3);
            }
        }

        #pragma unroll
        for (int jd = 0; jd < 8; jd++) {
            unsigned vf[8];
            ldsm4t(vf,     su(&Vs[s][(8 * lt + lr) * KSTR + 8 * jd]));
            ldsm4t(vf + 4, su(&Vs[s][(32 + 8 * lt + lr) * KSTR + 8 * jd]));
            #pragma unroll
            for (int mt = 0; mt < 2; mt++)
                #pragma unroll
                for (int kk2 = 0; kk2 < 4; kk2++)
                    mma16816(O[mt][jd], Ph[mt][kk2], vf[2 * kk2], vf[2 * kk2 + 1]);
        }
    }

    #pragma unroll
    for (int mt = 0; mt < 2; mt++) {
        float l0 = rl0[mt], l1 = rl1[mt];
        l0 += __shfl_xor_sync(0xffffffffu, l0, 1);
        l0 += __shfl_xor_sync(0xffffffffu, l0, 2);
        l1 += __shfl_xor_sync(0xffffffffu, l1, 1);
        l1 += __shfl_xor_sync(0xffffffffu, l1, 2);
        float inv0 = 1.0f / l0, inv1 = 1.0f / l1;
        size_t obase = ((size_t)b * NN + q0 + mt * 16) * 512 + h * 64;
        #pragma unroll
        for (int jd = 0; jd < 8; jd++) {
            int dim = 8 * jd + qq * 2;
            *(unsigned*)&g_af[obase + (size_t)gq * 512 + dim] =
                rnd2(O[mt][jd][0] * inv0, O[mt][jd][1] * inv0);
            *(unsigned*)&g_af[obase + (size_t)(gq + 8) * 512 + dim] =
                rnd2(O[mt][jd][2] * inv1, O[mt][jd][3] * inv1);
        }
    }
}

// ---------------- launch ----------------------------------------------------
extern "C" void kernel_launch(void* const* d_in, const int* in_sizes, int n_in,
                              void* d_out, int out_size) {
    const float* x     = (const float*)d_in[0];
    const float* mem   = (const float*)d_in[1];
    const float* ln_g  = (const float*)d_in[2];
    const float* ln_b  = (const float*)d_in[3];
    const float* w_qkv = (const float*)d_in[4];
    const float* w_out = (const float*)d_in[5];
    const float* b_out = (const float*)d_in[6];
    const float* pk_w  = (const float*)d_in[7];
    const float* pk_b  = (const float*)d_in[8];
    const float* pv_w  = (const float*)d_in[9];
    const float* pv_b  = (const float*)d_in[10];
    float* out = (float*)d_out;

    __half *wq, *wo;
    cudaGetSymbolAddress((void**)&wq, g_wq);
    cudaGetSymbolAddress((void**)&wo, g_wo);

    round_kernel<<<(DD * 3 * DD / 4 + 255) / 256, 256>>>(w_qkv, wq, DD * 3 * DD / 4);
    round_kernel<<<(DD * DD / 4 + 255) / 256, 256>>>(w_out, wo, DD * DD / 4);
    mem_round_kernel<<<(BB * MM * 512 / 4 + 255) / 256, 256>>>(mem);
    ln_kernel<<<BB * NN, 128>>>(x, ln_g, ln_b);
    mma_gemm_kernel<<<dim3(1536 / 128, (BB * NN) / 128), 256>>>(wq, nullptr, nullptr, 1536, 0);
    qnorm_kernel<<<BB * NN * HH / 8, 256>>>();
    peg_kernel<<<dim3(BB * NK, 2), 128>>>(pk_w, pk_b, pv_w, pv_b);
    attn_mma_kernel<<<dim3(NN / 128, BB * HH), 128>>>();
    mma_gemm_kernel<<<dim3(512 / 128, (BB * NN) / 128), 256>>>(wo, b_out, out, 512, 1);
}

// round 17
// speedup vs baseline: 1.0340x; 1.0340x over previous
#include <cuda_runtime.h>
#include <cuda_fp16.h>
#include <cstring>

#define BB 2
#define NN 4096
#define DD 512
#define HH 8
#define DH 64
#define MM 1024
#define NK 5120          // NN + MM
#define LSEQ 5119        // NK - 1

// ---------------- fp16 helpers -----------------------------------------------
__device__ __forceinline__ unsigned rnd2(float x, float y) {
    __half2 h = __floats2half2_rn(x, y);
    unsigned u; memcpy(&u, &h, 4); return u;
}
__device__ __forceinline__ void mma16816(float c[4], const unsigned a[4],
                                         unsigned b0, unsigned b1) {
    asm("mma.sync.aligned.m16n8k16.row.col.f32.f16.f16.f32 "
        "{%0,%1,%2,%3},{%4,%5,%6,%7},{%8,%9},{%0,%1,%2,%3};"
        : "+f"(c[0]), "+f"(c[1]), "+f"(c[2]), "+f"(c[3])
        : "r"(a[0]), "r"(a[1]), "r"(a[2]), "r"(a[3]), "r"(b0), "r"(b1));
}
__device__ __forceinline__ unsigned su(const void* p) {
    return (unsigned)__cvta_generic_to_shared(p);
}
__device__ __forceinline__ void ldsm4(unsigned* r, unsigned addr) {
    asm volatile("ldmatrix.sync.aligned.m8n8.x4.shared.b16 {%0,%1,%2,%3}, [%4];"
                 : "=r"(r[0]), "=r"(r[1]), "=r"(r[2]), "=r"(r[3]) : "r"(addr));
}
__device__ __forceinline__ void ldsm4t(unsigned* r, unsigned addr) {
    asm volatile("ldmatrix.sync.aligned.m8n8.x4.trans.shared.b16 {%0,%1,%2,%3}, [%4];"
                 : "=r"(r[0]), "=r"(r[1]), "=r"(r[2]), "=r"(r[3]) : "r"(addr));
}
__device__ __forceinline__ void cpa16(void* s, const void* g) {
    asm volatile("cp.async.cg.shared.global [%0], [%1], 16;" :: "r"(su(s)), "l"(g));
}
__device__ __forceinline__ void cp_commit() { asm volatile("cp.async.commit_group;"); }
__device__ __forceinline__ void cp_wait1()  { asm volatile("cp.async.wait_group 1;"); }
__device__ __forceinline__ void cp_wait0()  { asm volatile("cp.async.wait_group 0;"); }

// ---------------- scratch ----------------------------------------------------
__device__ __half    g_xf[BB * NN * DD];   // LN out fp16
__device__ __half    g_qf[BB * NN * DD];   // q, pre-scaled fp16
__device__ __half    g_kp[BB * NK * DD];   // pre-PEG k fp16 (tail = mem)
__device__ __half    g_vp[BB * NK * DD];   // pre-PEG v fp16 (tail = mem)
__device__ __half    g_kf[BB * NK * DD];   // post-PEG K fp16
__device__ __half    g_vf[BB * NK * DD];   // post-PEG V fp16
__device__ __half    g_af[BB * NN * DD];   // attention out fp16
__device__ __half    g_wq[DD * 3 * DD];    // w_qkv fp16
__device__ __half    g_wo[DD * DD];        // w_out fp16
__device__ float     g_mq[BB * NN * HH];   // ||q_row|| per head (q pre-scaled)
__device__ unsigned  g_mku[BB * HH];       // max_k ||k_k|| per (b,h), float-as-uint

// ---------------- fused prep: weight rounding + mem tails + mku init --------
#define WQ_N4 (DD * 3 * DD / 4)
#define WO_N4 (DD * DD / 4)
#define MEM_N4 (BB * MM * 512 / 4)
__global__ void prep_kernel(const float* __restrict__ w_qkv,
                            const float* __restrict__ w_out,
                            const float* __restrict__ mem) {
    int i = blockIdx.x * 256 + threadIdx.x;
    if (i < BB * HH) g_mku[i] = 0u;
    if (i < WQ_N4) {
        float4 v = ((const float4*)w_qkv)[i];
        ((uint2*)g_wq)[i] = make_uint2(rnd2(v.x, v.y), rnd2(v.z, v.w));
    }
    if (i < WO_N4) {
        float4 v = ((const float4*)w_out)[i];
        ((uint2*)g_wo)[i] = make_uint2(rnd2(v.x, v.y), rnd2(v.z, v.w));
    }
    if (i < MEM_N4) {
        float4 v = ((const float4*)mem)[i];
        uint2 pk = make_uint2(rnd2(v.x, v.y), rnd2(v.z, v.w));
        int gi = i << 2;
        int b = gi / (MM * 512);
        int rem = gi - b * (MM * 512);
        size_t off = (((size_t)b * NK + NN) * 512 + rem) >> 2;
        ((uint2*)g_kp)[off] = pk;
        ((uint2*)g_vp)[off] = pk;
    }
}

// ---------------- LayerNorm (writes fp16) ------------------------------------
__global__ void ln_kernel(const float* __restrict__ x,
                          const float* __restrict__ g,
                          const float* __restrict__ bt) {
    int row = blockIdx.x;
    int t = threadIdx.x;
    const float4* xr = (const float4*)(x + (size_t)row * DD);
    float4 v = xr[t];
    float s  = v.x + v.y + v.z + v.w;
    float s2 = v.x*v.x + v.y*v.y + v.z*v.z + v.w*v.w;
    #pragma unroll
    for (int o = 16; o > 0; o >>= 1) {
        s  += __shfl_xor_sync(0xffffffffu, s,  o);
        s2 += __shfl_xor_sync(0xffffffffu, s2, o);
    }
    __shared__ float a1[4], a2[4];
    int w = t >> 5;
    if ((t & 31) == 0) { a1[w] = s; a2[w] = s2; }
    __syncthreads();
    s  = a1[0] + a1[1] + a1[2] + a1[3];
    s2 = a2[0] + a2[1] + a2[2] + a2[3];
    float mu  = s * (1.0f / 512.0f);
    float var = s2 * (1.0f / 512.0f) - mu * mu;
    float rs  = rsqrtf(var + 1e-5f);
    float4 gg = ((const float4*)g)[t];
    float4 bb = ((const float4*)bt)[t];
    float4 o4;
    o4.x = (v.x - mu) * rs * gg.x + bb.x;
    o4.y = (v.y - mu) * rs * gg.y + bb.y;
    o4.z = (v.z - mu) * rs * gg.z + bb.z;
    o4.w = (v.w - mu) * rs * gg.w + bb.w;
    ((uint2*)(g_xf + (size_t)row * DD))[t] =
        make_uint2(rnd2(o4.x, o4.y), rnd2(o4.z, o4.w));
}

// ---------------- q norms: one warp per (b*NN+n, h) --------------------------
__global__ void qnorm_kernel() {
    int idx = blockIdx.x * 8 + (threadIdx.x >> 5);
    int lane = threadIdx.x & 31;
    int bn = idx >> 3, h = idx & 7;
    unsigned u = *(const unsigned*)(g_qf + (size_t)bn * 512 + h * 64 + lane * 2);
    __half2 hv; memcpy(&hv, &u, 4);
    float2 f = __half22float2(hv);
    float s = f.x * f.x + f.y * f.y;
    #pragma unroll
    for (int o = 16; o > 0; o >>= 1) s += __shfl_xor_sync(0xffffffffu, s, o);
    if (lane == 0) g_mq[idx] = sqrtf(s);
}

// ---------------- fp16 1-term mma GEMM, 128x128 tile, 3-stage cp.async ------
#define ASTR 24
#define WSTR 136
__global__ __launch_bounds__(256)
void mma_gemm_kernel(const __half* __restrict__ Wh,
                     const float* __restrict__ bias,
                     float* __restrict__ dout, int cn, int mode) {
    const __half* Ah = mode ? g_af : g_xf;
    __shared__ __align__(16) __half sA[3][128 * ASTR];
    __shared__ __align__(16) __half sW[3][16 * WSTR];
    int tid = threadIdx.x, w = tid >> 5, lane = tid & 31;
    int gq = lane >> 2, qq = lane & 3;
    int lt = lane >> 3, lr = lane & 7;
    int row0 = blockIdx.y * 128, col0 = blockIdx.x * 128;
    int wm = w >> 1, wn = w & 1;
    float acc[2][8][4];
    #pragma unroll
    for (int mf = 0; mf < 2; mf++)
        #pragma unroll
        for (int nf = 0; nf < 8; nf++)
            #pragma unroll
            for (int c = 0; c < 4; c++) acc[mf][nf][c] = 0.f;

    auto load_tile = [&](int t, int s) {
        int kt = t * 16;
        {
            int r = tid >> 1, e = tid & 1;
            cpa16(&sA[s][r * ASTR + 8 * e], Ah + (size_t)(row0 + r) * 512 + kt + 8 * e);
        }
        {
            int r = tid >> 4, e = tid & 15;
            cpa16(&sW[s][r * WSTR + 8 * e], Wh + (size_t)(kt + r) * cn + col0 + 8 * e);
        }
        cp_commit();
    };

    load_tile(0, 0);
    load_tile(1, 1);
    for (int t = 0; t < 32; t++) {
        int s = t % 3;
        if (t + 2 < 32) cp_wait1(); else cp_wait0();
        __syncthreads();
        if (t + 2 < 32) load_tile(t + 2, (t + 2) % 3);
        unsigned ah[2][4];
        #pragma unroll
        for (int mf = 0; mf < 2; mf++) {
            int ar = wm * 32 + mf * 16 + (lt & 1) * 8 + lr;
            int ak = (lt >> 1) * 8;
            ldsm4(ah[mf], su(&sA[s][ar * ASTR + ak]));
        }
        unsigned bh[4][4];
        #pragma unroll
        for (int nh = 0; nh < 4; nh++) {
            int br = (lt & 1) * 8 + lr;
            int bc = wn * 64 + nh * 16 + (lt >> 1) * 8;
            ldsm4t(bh[nh], su(&sW[s][br * WSTR + bc]));
        }
        #pragma unroll
        for (int nf = 0; nf < 8; nf++) {
            unsigned b0 = bh[nf >> 1][(nf & 1) * 2];
            unsigned b1 = bh[nf >> 1][(nf & 1) * 2 + 1];
            #pragma unroll
            for (int mf = 0; mf < 2; mf++)
                mma16816(acc[mf][nf], ah[mf], b0, b1);
        }
    }
    #pragma unroll
    for (int mf = 0; mf < 2; mf++) {
        int rlo = row0 + wm * 32 + mf * 16 + gq;
        #pragma unroll
        for (int nf = 0; nf < 8; nf++) {
            int cl = col0 + wn * 64 + nf * 8 + 2 * qq;
            float* c = acc[mf][nf];
            if (mode == 0) {
                int sel = cl >> 9, c5 = cl & 511;
                #pragma unroll
                for (int half_ = 0; half_ < 2; half_++) {
                    int rr = rlo + half_ * 8;
                    int b = rr >> 12, n = rr & 4095;
                    float v0 = c[2 * half_], v1 = c[2 * half_ + 1];
                    if (sel == 0)
                        *(unsigned*)&g_qf[((size_t)b * NN + n) * 512 + c5] =
                            rnd2(v0 * 0.125f, v1 * 0.125f);
                    else if (sel == 1)
                        *(unsigned*)&g_kp[((size_t)b * NK + n) * 512 + c5] = rnd2(v0, v1);
                    else
                        *(unsigned*)&g_vp[((size_t)b * NK + n) * 512 + c5] = rnd2(v0, v1);
                }
            } else {
                float2 bq = *(const float2*)(bias + cl);
                float2 o0; o0.x = c[0] + bq.x; o0.y = c[1] + bq.y;
                float2 o1; o1.x = c[2] + bq.x; o1.y = c[3] + bq.y;
                *(float2*)(dout + (size_t)rlo * 512 + cl)       = o0;
                *(float2*)(dout + (size_t)(rlo + 8) * 512 + cl) = o1;
            }
        }
    }
}

// ---------------- PEG1D depthwise conv (fp16 in/out) + K norm atomicMax -----
__global__ void peg_kernel(const float* __restrict__ wk, const float* __restrict__ bk,
                           const float* __restrict__ wv, const float* __restrict__ bv) {
    int which = blockIdx.y;
    const float* w    = which ? wv : wk;
    const float* bias = which ? bv : bk;
    const __half* src = which ? g_vp : g_kp;
    __half* df        = which ? g_vf : g_kf;
    int gr = blockIdx.x;
    int b = gr / NK, r = gr - b * NK;
    int tx = threadIdx.x;
    int c = tx << 2;
    const __half* base = src + (size_t)b * NK * 512;
    auto ld4 = [&](int row) -> float4 {
        uint2 u = *(const uint2*)(base + (size_t)row * 512 + c);
        __half2 h0, h1;
        memcpy(&h0, &u.x, 4); memcpy(&h1, &u.y, 4);
        float2 f0 = __half22float2(h0), f1 = __half22float2(h1);
        return make_float4(f0.x, f0.y, f1.x, f1.y);
    };
    float4 xc = ld4(r);
    size_t doff = ((size_t)b * NK + r) * 512 + c;
    float4 o4;
    if (r == 0) {
        o4 = xc;
    } else {
        int t = r - 1;
        float w0[4], w1[4], w2[4];
        #pragma unroll
        for (int j = 0; j < 4; j++) {
            w0[j] = __ldg(w + (c + j) * 3 + 0);
            w1[j] = __ldg(w + (c + j) * 3 + 1);
            w2[j] = __ldg(w + (c + j) * 3 + 2);
        }
        float4 bb = *(const float4*)(bias + c);
        const float4 z4 = make_float4(0.f, 0.f, 0.f, 0.f);
        int p = t & 31;
        float4 L1 = (p > 0)                 ? ld4(r - 1) : z4;
        float4 R1 = (p < 31 && t + 1 < LSEQ)? ld4(r + 1) : z4;
        int u   = (t + 16) % LSEQ;
        int p2p = u % 32;
        int jl  = (u + LSEQ - 17) % LSEQ;
        int jr  = (u + LSEQ - 15) % LSEQ;
        float4 L2 = (p2p > 0)                  ? ld4(1 + jl) : z4;
        float4 R2 = (p2p < 31 && u + 1 < LSEQ) ? ld4(1 + jr) : z4;
        o4.x = xc.x + (w0[0]*L1.x + w1[0]*xc.x + w2[0]*R1.x + bb.x)
                    + (w0[0]*L2.x + w1[0]*xc.x + w2[0]*R2.x + bb.x);
        o4.y = xc.y + (w0[1]*L1.y + w1[1]*xc.y + w2[1]*R1.y + bb.y)
                    + (w0[1]*L2.y + w1[1]*xc.y + w2[1]*R2.y + bb.y);
        o4.z = xc.z + (w0[2]*L1.z + w1[2]*xc.z + w2[2]*R1.z + bb.z)
                    + (w0[2]*L2.z + w1[2]*xc.z + w2[2]*R2.z + bb.z);
        o4.w = xc.w + (w0[3]*L1.w + w1[3]*xc.w + w2[3]*R1.w + bb.w)
                    + (w0[3]*L2.w + w1[3]*xc.w + w2[3]*R2.w + bb.w);
    }
    *(uint2*)(df + doff) = make_uint2(rnd2(o4.x, o4.y), rnd2(o4.z, o4.w));
    if (which == 0) {
        float s = o4.x*o4.x + o4.y*o4.y + o4.z*o4.z + o4.w*o4.w;
        #pragma unroll
        for (int o = 8; o > 0; o >>= 1)
            s += __shfl_xor_sync(0xffffffffu, s, o);
        if ((tx & 15) == 0) {
            int head = tx >> 4;
            atomicMax(&g_mku[b * HH + head], __float_as_uint(sqrtf(s) * 1.001f));
        }
    }
}

// ---------------- flash attention: static-bound softmax (R15 shape) ---------
#define KSTR 72
__global__ __launch_bounds__(256, 2)
void attn_mma_kernel() {
    __shared__ __align__(16) __half Ks[2][64 * KSTR];
    __shared__ __align__(16) __half Vs[2][64 * KSTR];
    int tid = threadIdx.x;
    int w = tid >> 5, lane = tid & 31;
    int gq = lane >> 2, qq = lane & 3;
    int lt = lane >> 3, lr = lane & 7;
    int bh_ = blockIdx.y;
    int b = bh_ >> 3, h = bh_ & 7;
    int q0 = blockIdx.x * 128 + w * 16;

    const __half* kfb = g_kf + ((size_t)b * NK) * 512 + h * 64;
    const __half* vfb = g_vf + ((size_t)b * NK) * 512 + h * 64;

    auto load_tile = [&](int kt, int s) {
        #pragma unroll
        for (int i = 0; i < 2; i++) {
            int idx = tid + 256 * i;
            int row = idx >> 3, e = idx & 7;
            size_t goff = (size_t)(kt + row) * 512 + 8 * e;
            int soff = row * KSTR + 8 * e;
            cpa16(&Ks[s][soff], kfb + goff);
            cpa16(&Vs[s][soff], vfb + goff);
        }
        cp_commit();
    };

    unsigned qh[4][4];
    {
        const __half* qbase = g_qf + ((size_t)b * NN + q0) * 512 + h * 64;
        #pragma unroll
        for (int kk = 0; kk < 4; kk++)
            #pragma unroll
            for (int cc = 0; cc < 2; cc++)
                #pragma unroll
                for (int rr = 0; rr < 2; rr++) {
                    int row = gq + rr * 8;
                    int dim = kk * 16 + cc * 8 + qq * 2;
                    qh[kk][rr + 2 * cc] = *(const unsigned*)(qbase + (size_t)row * 512 + dim);
                }
    }
    float mk = __uint_as_float(g_mku[b * HH + h]);
    float m0 = g_mq[((size_t)b * NN + q0 + gq)     * HH + h] * mk;
    float m1 = g_mq[((size_t)b * NN + q0 + gq + 8) * HH + h] * mk;

    float O[8][4];
    #pragma unroll
    for (int j = 0; j < 8; j++)
        #pragma unroll
        for (int c = 0; c < 4; c++) O[j][c] = 0.f;
    float rl0 = 0.f, rl1 = 0.f;

    load_tile(0, 0);
    const int NT = NK / 64;
    for (int t = 0; t < NT; t++) {
        int s = t & 1;
        cp_wait0();
        __syncthreads();
        if (t + 1 < NT) load_tile((t + 1) * 64, s ^ 1);

        unsigned Ph[4][4];
        #pragma unroll
        for (int j = 0; j < 8; j++) {
            unsigned bf[8];
            int krow = (8 * j + lr) * KSTR;
            ldsm4(bf,     su(&Ks[s][krow + 8 * lt]));
            ldsm4(bf + 4, su(&Ks[s][krow + 32 + 8 * lt]));
            float c[4] = {0.f, 0.f, 0.f, 0.f};
            #pragma unroll
            for (int kk = 0; kk < 4; kk++)
                mma16816(c, qh[kk], bf[2 * kk], bf[2 * kk + 1]);
            float p0 = __expf(c[0] - m0);
            float p1 = __expf(c[1] - m0);
            float p2 = __expf(c[2] - m1);
            float p3 = __expf(c[3] - m1);
            rl0 += p0 + p1; rl1 += p2 + p3;
            int kk2 = j >> 1, half_ = j & 1;
            Ph[kk2][2 * half_]     = rnd2(p0, p1);
            Ph[kk2][2 * half_ + 1] = rnd2(p2, p3);
        }

        #pragma unroll
        for (int jd = 0; jd < 8; jd++) {
            unsigned vf[8];
            ldsm4t(vf,     su(&Vs[s][(8 * lt + lr) * KSTR + 8 * jd]));
            ldsm4t(vf + 4, su(&Vs[s][(32 + 8 * lt + lr) * KSTR + 8 * jd]));
            #pragma unroll
            for (int kk2 = 0; kk2 < 4; kk2++)
                mma16816(O[jd], Ph[kk2], vf[2 * kk2], vf[2 * kk2 + 1]);
        }
    }

    float l0 = rl0, l1 = rl1;
    l0 += __shfl_xor_sync(0xffffffffu, l0, 1);
    l0 += __shfl_xor_sync(0xffffffffu, l0, 2);
    l1 += __shfl_xor_sync(0xffffffffu, l1, 1);
    l1 += __shfl_xor_sync(0xffffffffu, l1, 2);
    float inv0 = 1.0f / l0, inv1 = 1.0f / l1;
    size_t obase = ((size_t)b * NN + q0) * 512 + h * 64;
    #pragma unroll
    for (int jd = 0; jd < 8; jd++) {
        int dim = 8 * jd + qq * 2;
        *(unsigned*)&g_af[obase + (size_t)gq * 512 + dim] =
            rnd2(O[jd][0] * inv0, O[jd][1] * inv0);
        *(unsigned*)&g_af[obase + (size_t)(gq + 8) * 512 + dim] =
            rnd2(O[jd][2] * inv1, O[jd][3] * inv1);
    }
}

// ---------------- launch ----------------------------------------------------
extern "C" void kernel_launch(void* const* d_in, const int* in_sizes, int n_in,
                              void* d_out, int out_size) {
    const float* x     = (const float*)d_in[0];
    const float* mem   = (const float*)d_in[1];
    const float* ln_g  = (const float*)d_in[2];
    const float* ln_b  = (const float*)d_in[3];
    const float* w_qkv = (const float*)d_in[4];
    const float* w_out = (const float*)d_in[5];
    const float* b_out = (const float*)d_in[6];
    const float* pk_w  = (const float*)d_in[7];
    const float* pk_b  = (const float*)d_in[8];
    const float* pv_w  = (const float*)d_in[9];
    const float* pv_b  = (const float*)d_in[10];
    float* out = (float*)d_out;

    __half *wq, *wo;
    cudaGetSymbolAddress((void**)&wq, g_wq);
    cudaGetSymbolAddress((void**)&wo, g_wo);

    prep_kernel<<<(MEM_N4 + 255) / 256, 256>>>(w_qkv, w_out, mem);
    ln_kernel<<<BB * NN, 128>>>(x, ln_g, ln_b);
    mma_gemm_kernel<<<dim3(1536 / 128, (BB * NN) / 128), 256>>>(wq, nullptr, nullptr, 1536, 0);
    qnorm_kernel<<<BB * NN * HH / 8, 256>>>();
    peg_kernel<<<dim3(BB * NK, 2), 128>>>(pk_w, pk_b, pv_w, pv_b);
    attn_mma_kernel<<<dim3(NN / 128, BB * HH), 256>>>();
    mma_gemm_kernel<<<dim3(512 / 128, (BB * NN) / 128), 256>>>(wo, b_out, out, 512, 1);
}